// round 13
// baseline (speedup 1.0000x reference)
#include <cuda_runtime.h>
#include <cuda_bf16.h>
#include <math.h>

// Problem constants
#define BB 32
#define NN 1000
#define CC 64
#define HF 12
#define WF 20
#define DD 768          // C*HF
#define NM1 999         // N-1
#define YD 72
#define OUTC 77         // 2 + 2 + 73
#define HN 75           // heads output cols (2 cls + 73 reg)
#define BT_N 1024       // attn_w padded col count (8 full 128-blocks)
#define SK_PAD 1024     // S padded k count (32 full 32-blocks)
#define WN 128          // heads W padded col count

// GEMM smem layout (floats)
#define SA_STRIDE 36            // 32 k + 4 pad
#define SB_STRIDE 132           // 128 n + 4 pad
#define SA_STAGE  (128 * SA_STRIDE)   // 4608
#define SB_STAGE  (32 * SB_STRIDE)    // 4224
#define SB_BASE   (2 * SA_STAGE)      // 9216
#define GEMM_SMEM ((2 * SA_STAGE + 2 * SB_STAGE) * 4)   // 70656 bytes

// ---------------------------------------------------------------------------
// Scratch (device globals; no runtime allocation allowed)
// ---------------------------------------------------------------------------
__device__ float g_featA[BB * NN * DD];       // A-permuted, tf32-rounded
__device__ float g_featB[BB * NN * DD];       // B-permuted, tf32-rounded
__device__ float g_logits[BB * NN * NM1];     // fp32
__device__ float g_S[BB * NN * SK_PAD];       // A-permuted softmax, padded, rounded
__device__ float g_att[BB * NN * DD];         // A-permuted, tf32-rounded
__device__ float g_ho[BB * NN * HN];          // heads GEMM result (32000 x 75)
__device__ float g_W[2 * DD * WN];            // B-permuted heads weights, padded
__device__ float g_Bt[DD * BT_N];             // B-permuted attn_w, padded
__device__ int   g_mask_mode;                 // 1 = byte mask, 0 = 4-byte mask

// ---------------------------------------------------------------------------
// Permutation helpers
//   permA: within each 32-k block, pos = (k&3)*8 + (k>>2)&7
//   permB: within each 128-n block, pos = (n&7)*16 + (n>>3)&15
// ---------------------------------------------------------------------------
__device__ __forceinline__ int permA(int k)
{
    return (k & ~31) | (((k & 3) << 3) | ((k >> 2) & 7));
}
__device__ __forceinline__ int permB(int n)
{
    return (n & ~127) | (((n & 7) << 4) | ((n >> 3) & 15));
}

// ---------------------------------------------------------------------------
// PTX helpers
// ---------------------------------------------------------------------------
__device__ __forceinline__ unsigned int smem_u32(const void* p)
{
    unsigned int a;
    asm("{ .reg .u64 t; cvta.to.shared.u64 t, %1; cvt.u32.u64 %0, t; }"
        : "=r"(a) : "l"(p));
    return a;
}

__device__ __forceinline__ void cp_async16(unsigned int dst, const void* src, int sz)
{
    asm volatile("cp.async.ca.shared.global [%0], [%1], 16, %2;"
                 :: "r"(dst), "l"(src), "r"(sz));
}

__device__ __forceinline__ void cp_commit()
{
    asm volatile("cp.async.commit_group;");
}

template<int N>
__device__ __forceinline__ void cp_wait()
{
    asm volatile("cp.async.wait_group %0;" :: "n"(N));
}

__device__ __forceinline__ float f2tf32f(float f)
{
    unsigned int r;
    asm("cvt.rna.tf32.f32 %0, %1;" : "=r"(r) : "f"(f));
    return __uint_as_float(r);
}

// ---------------------------------------------------------------------------
// Mask dtype detection (bool/uint8 vs int32/float32)
// ---------------------------------------------------------------------------
__global__ __launch_bounds__(256)
void detect_mask_kernel(const unsigned int* __restrict__ w, int nwords)
{
    __shared__ int bad;
    if (threadIdx.x == 0) bad = 0;
    __syncthreads();
    int local = 0;
    for (int k = threadIdx.x; k < nwords; k += blockDim.x) {
        unsigned int v = w[k];
        if (v != 0u && v != 1u && v != 0x3F800000u) local = 1;
    }
    if (local) bad = 1;
    __syncthreads();
    if (threadIdx.x == 0) g_mask_mode = bad;   // 1 => byte mask
}

// ---------------------------------------------------------------------------
// Gather: writes tf32-rounded feat in BOTH A-permuted and B-permuted layouts
// ---------------------------------------------------------------------------
__global__ __launch_bounds__(256)
void gather_kernel(const float* __restrict__ fv,
                   const int* __restrict__ z,
                   const int* __restrict__ y,
                   const int* __restrict__ x,
                   const void* __restrict__ mask,
                   float* __restrict__ featA,
                   float* __restrict__ featB,
                   int total)
{
    int idx = blockIdx.x * blockDim.x + threadIdx.x;
    if (idx >= total) return;
    int d = idx % DD;
    int rest = idx / DD;
    int n = rest % NN;
    int b = rest / NN;
    int nd = n * DD + d;

    bool inv;
    if (g_mask_mode)
        inv = ((const unsigned char*)mask)[nd] != 0;
    else
        inv = ((const unsigned int*)mask)[nd] != 0u;

    float v = 0.f;
    if (!inv) {
        int zz = z[nd], yy = y[nd], xx = x[nd];
        v = fv[((b * CC + zz) * HF + yy) * WF + xx];
    }
    v = f2tf32f(v);
    size_t rowb = (size_t)(b * NN + n) * DD;
    featA[rowb + permA(d)] = v;
    featB[rowb + permB(d)] = v;
}

// ---------------------------------------------------------------------------
// Prep attn_w: pad 999 -> 1024 cols, B-permute, tf32 round.
// ---------------------------------------------------------------------------
__global__ __launch_bounds__(256)
void prep_attnw_kernel(const float* __restrict__ w, float* __restrict__ out)
{
    int idx = blockIdx.x * blockDim.x + threadIdx.x;
    if (idx >= DD * BT_N) return;
    int k = idx / BT_N, n = idx % BT_N;
    out[k * BT_N + permB(n)] = (n < NM1) ? f2tf32f(w[k * NM1 + n]) : 0.f;
}

// ---------------------------------------------------------------------------
// Pack heads weights: [cls|reg] -> 128-wide B-permuted rows, tf32-rounded
// ---------------------------------------------------------------------------
__global__ __launch_bounds__(256)
void pack_w_kernel(const float* __restrict__ cls_w,
                   const float* __restrict__ reg_w,
                   float* __restrict__ W)
{
    int idx = blockIdx.x * blockDim.x + threadIdx.x;
    if (idx >= 2 * DD * WN) return;
    int k = idx / WN, c = idx % WN;
    float v = 0.f;
    if (c < 2)       v = f2tf32f(cls_w[k * 2 + c]);
    else if (c < HN) v = f2tf32f(reg_w[k * 73 + (c - 2)]);
    W[k * WN + permB(c)] = v;
}

// ---------------------------------------------------------------------------
// TF32 tensor-core GEMM, 128x128 block, Ktile 32, 128 threads, 4 warps,
// warp tile 64x64.  Operands pre-rounded AND pre-permuted:
//   A global: permA within 32-k blocks  -> As[m][pos] stride 36
//   B global: permB within 128-n blocks -> Bs[k][pos] stride 132
// Fragment loads are all LDS.128, conflict-free.  2-stage cp.async pipeline,
// one __syncthreads per K-tile.  All staging is 16B cp.async.
// MODE 0: plain A (stride lda). MODE 1: concat A=[A1|A2] rows of DD each.
// PERM_ROUND_OUT: tf32-round + A-permute output columns (GEMM2 -> att).
// K: loop/A extent (multiple of 32). Kb: valid B rows (zero-fill beyond).
// ---------------------------------------------------------------------------
template<int MODE, bool ADD_BIAS, bool PERM_ROUND_OUT>
__global__ __launch_bounds__(128, 2)
void gemm_tf32_cp_kernel(const float* __restrict__ A,
                         const float* __restrict__ A2,
                         const float* __restrict__ B,
                         const float* __restrict__ bias,
                         float* __restrict__ C,
                         int M, int N, int K, int Kb, int lda, int ldb,
                         size_t sA, size_t sB, size_t sC)
{
    extern __shared__ float sm[];

    const int tid  = threadIdx.x;
    const int lane = tid & 31;
    const int wid  = tid >> 5;          // 0..3
    const int gid  = lane >> 2;         // 0..7
    const int tg   = lane & 3;          // 0..3
    const int wm   = (wid & 1) * 64;
    const int wn   = (wid >> 1) * 64;

    const int m0 = blockIdx.y * 128;
    const int n0 = blockIdx.x * 128;

    if (MODE == 0) A += (size_t)blockIdx.z * sA;
    B += (size_t)blockIdx.z * sB;
    C += (size_t)blockIdx.z * sC;

    const unsigned int smA_u = smem_u32(sm);
    const unsigned int smB_u = smem_u32(sm + SB_BASE);

    float acc[4][8][4];
    #pragma unroll
    for (int i = 0; i < 4; i++)
        #pragma unroll
        for (int j = 0; j < 8; j++)
            #pragma unroll
            for (int q = 0; q < 4; q++) acc[i][j][q] = 0.f;

    // ---- stage: cp.async A-tile and B-tile for kt into stage st (16B only)
    auto stage = [&](int kt, int st) {
        unsigned int abase = smA_u + st * (SA_STAGE * 4);
        #pragma unroll
        for (int i = 0; i < 8; i++) {
            int c   = tid + i * 128;
            int m_l = c >> 3, kq = c & 7;
            int m = m0 + m_l, kg = kt + kq * 4;
            const float* src = A;
            int sz = 0;
            if (m < M && kg < K) {
                if (MODE == 1)
                    src = (kg < DD) ? &A[(size_t)m * DD + kg]
                                    : &A2[(size_t)m * DD + (kg - DD)];
                else
                    src = &A[(size_t)m * lda + kg];
                sz = 16;
            }
            cp_async16(abase + (m_l * SA_STRIDE + kq * 4) * 4, src, sz);
        }
        unsigned int bbase = smB_u + st * (SB_STAGE * 4);
        #pragma unroll
        for (int i = 0; i < 8; i++) {
            int c   = tid + i * 128;
            int k_l = c >> 5, nq = c & 31;
            int kg = kt + k_l;
            const float* src = (kg < Kb) ? &B[(size_t)kg * ldb + n0 + nq * 4] : B;
            int sz = (kg < Kb) ? 16 : 0;
            cp_async16(bbase + (k_l * SB_STRIDE + nq * 4) * 4, src, sz);
        }
    };

    const int aoff = tg * 8;
    const int boff = gid * 16 + 8 * (wid >> 1);

    auto compute = [&](int st) {
        const unsigned int* Ab = (const unsigned int*)(sm + st * SA_STAGE);
        const unsigned int* Bb = (const unsigned int*)(sm + SB_BASE + st * SB_STAGE);
        #pragma unroll
        for (int half = 0; half < 2; half++) {
            uint4 ra[8];
            #pragma unroll
            for (int mt = 0; mt < 4; mt++) {
                int ar = wm + mt * 16 + gid;
                ra[mt * 2]     = *(const uint4*)(Ab + ar * SA_STRIDE + aoff + half * 4);
                ra[mt * 2 + 1] = *(const uint4*)(Ab + (ar + 8) * SA_STRIDE + aoff + half * 4);
            }
            #pragma unroll
            for (int kss = 0; kss < 2; kss++) {
                const int ks = half * 2 + kss;
                const unsigned int* r0 = Bb + (8 * ks + tg) * SB_STRIDE + boff;
                const unsigned int* r1 = Bb + (8 * ks + tg + 4) * SB_STRIDE + boff;
                uint4 b0a = *(const uint4*)r0;
                uint4 b0b = *(const uint4*)(r0 + 4);
                uint4 b1a = *(const uint4*)r1;
                uint4 b1b = *(const uint4*)(r1 + 4);
                unsigned int bf0[8] = {b0a.x, b0a.y, b0a.z, b0a.w,
                                       b0b.x, b0b.y, b0b.z, b0b.w};
                unsigned int bf1[8] = {b1a.x, b1a.y, b1a.z, b1a.w,
                                       b1b.x, b1b.y, b1b.z, b1b.w};
                #pragma unroll
                for (int mt = 0; mt < 4; mt++) {
                    const unsigned int* rl = (const unsigned int*)&ra[mt * 2];
                    const unsigned int* rh = (const unsigned int*)&ra[mt * 2 + 1];
                    unsigned int a0 = rl[kss * 2];
                    unsigned int a1 = rh[kss * 2];
                    unsigned int a2 = rl[kss * 2 + 1];
                    unsigned int a3 = rh[kss * 2 + 1];
                    #pragma unroll
                    for (int nt = 0; nt < 8; nt++) {
                        asm volatile(
                            "mma.sync.aligned.m16n8k8.row.col.f32.tf32.tf32.f32 "
                            "{%0,%1,%2,%3}, {%4,%5,%6,%7}, {%8,%9}, {%0,%1,%2,%3};\n"
                            : "+f"(acc[mt][nt][0]), "+f"(acc[mt][nt][1]),
                              "+f"(acc[mt][nt][2]), "+f"(acc[mt][nt][3])
                            : "r"(a0), "r"(a1), "r"(a2), "r"(a3),
                              "r"(bf0[nt]), "r"(bf1[nt]));
                    }
                }
            }
        }
    };

    // ---- 2-stage pipeline, one sync per tile ----
    stage(0, 0);
    cp_commit();

    int st = 0;
    for (int kt = 0; kt < K; kt += 32) {
        cp_wait<0>();
        __syncthreads();
        if (kt + 32 < K) {
            stage(kt + 32, st ^ 1);
            cp_commit();
        }
        compute(st);
        st ^= 1;
    }

    // ---- epilogue ----
    #pragma unroll
    for (int mt = 0; mt < 4; mt++) {
        #pragma unroll
        for (int nt = 0; nt < 8; nt++) {
            int row0 = m0 + wm + mt * 16 + gid;
            int col0 = n0 + wn + nt * 8 + tg * 2;
            #pragma unroll
            for (int q = 0; q < 4; q++) {
                int row = row0 + (q >> 1) * 8;
                int col = col0 + (q & 1);
                if (row < M && col < N) {
                    float v = acc[mt][nt][q];
                    if (ADD_BIAS) v += bias[col];
                    if (PERM_ROUND_OUT) {
                        C[(size_t)row * N + permA(col)] = f2tf32f(v);
                    } else {
                        C[(size_t)row * N + col] = v;
                    }
                }
            }
        }
    }
}

// ---------------------------------------------------------------------------
// Row softmax over 999 logits + scatter into padded (N x 1024) A-permuted S
// with zero diagonal and zeroed pad slots.
// ---------------------------------------------------------------------------
__global__ __launch_bounds__(256)
void softmax_scatter_kernel(const float* __restrict__ logits,
                            float* __restrict__ S)
{
    const int i = blockIdx.x;
    const int b = blockIdx.y;
    const float* __restrict__ row = logits + ((size_t)(b * NN + i)) * NM1;
    float* __restrict__ o = S + ((size_t)(b * NN + i)) * SK_PAD;

    __shared__ float sh[8];
    const int tid = threadIdx.x;
    const int lane = tid & 31, warp = tid >> 5;

    float rv[4];
    #pragma unroll
    for (int p = 0; p < 4; p++) {
        int k = tid + 256 * p;
        rv[p] = (k < NM1) ? row[k] : -1e30f;
    }

    float m = -1e30f;
    #pragma unroll
    for (int p = 0; p < 4; p++) m = fmaxf(m, rv[p]);
    #pragma unroll
    for (int off = 16; off; off >>= 1) m = fmaxf(m, __shfl_xor_sync(0xffffffffu, m, off));
    if (lane == 0) sh[warp] = m;
    __syncthreads();
    if (warp == 0) {
        float t = (lane < 8) ? sh[lane] : -1e30f;
        #pragma unroll
        for (int off = 16; off; off >>= 1) t = fmaxf(t, __shfl_xor_sync(0xffffffffu, t, off));
        if (lane == 0) sh[0] = t;
    }
    __syncthreads();
    m = sh[0];
    __syncthreads();

    float s = 0.f;
    float ev[4];
    #pragma unroll
    for (int p = 0; p < 4; p++) {
        int k = tid + 256 * p;
        float e = (k < NM1) ? __expf(rv[p] - m) : 0.f;
        ev[p] = e;
        s += e;
    }
    #pragma unroll
    for (int off = 16; off; off >>= 1) s += __shfl_xor_sync(0xffffffffu, s, off);
    if (lane == 0) sh[warp] = s;
    __syncthreads();
    if (warp == 0) {
        float t = (lane < 8) ? sh[lane] : 0.f;
        #pragma unroll
        for (int off = 16; off; off >>= 1) t += __shfl_xor_sync(0xffffffffu, t, off);
        if (lane == 0) sh[0] = t;
    }
    __syncthreads();
    const float inv = 1.f / sh[0];

    #pragma unroll
    for (int p = 0; p < 4; p++) {
        int k = tid + 256 * p;
        if (k < NM1) {
            int j = (k < i) ? k : k + 1;
            o[permA(j)] = f2tf32f(ev[p] * inv);
        }
    }
    if (tid == 0) o[permA(i)] = 0.f;
    // zero the 24 pad slots (logical k 1000..1023)
    if (tid < 24) o[permA(1000 + tid)] = 0.f;
}

// ---------------------------------------------------------------------------
// Heads epilogue: out[r][c] from ho (32000 x 75), biases, anchors.
// ---------------------------------------------------------------------------
__global__ __launch_bounds__(256)
void heads_epilogue_kernel(const float* __restrict__ ho,
                           const float* __restrict__ cls_b,
                           const float* __restrict__ reg_b,
                           const float* __restrict__ anchors,
                           float* __restrict__ out)
{
    int idx = blockIdx.x * blockDim.x + threadIdx.x;
    if (idx >= BB * NN * OUTC) return;
    int c = idx % OUTC;
    int r = idx / OUTC;
    int n = r % NN;
    float v;
    if (c < 2)       v = ho[(size_t)r * HN + c] + cls_b[c];
    else if (c < 4)  v = anchors[n * OUTC + c];
    else             v = ho[(size_t)r * HN + (c - 2)] + reg_b[c - 4]
                         + anchors[n * OUTC + c];
    out[idx] = v;
}

// ---------------------------------------------------------------------------
// Launch
// ---------------------------------------------------------------------------
extern "C" void kernel_launch(void* const* d_in, const int* in_sizes, int n_in,
                              void* d_out, int out_size)
{
    const float* fv      = (const float*)d_in[0];
    const float* attn_w  = (const float*)d_in[1];
    const float* attn_b  = (const float*)d_in[2];
    const float* cls_w   = (const float*)d_in[3];
    const float* cls_b   = (const float*)d_in[4];
    const float* reg_w   = (const float*)d_in[5];
    const float* reg_b   = (const float*)d_in[6];
    const float* anchors = (const float*)d_in[7];
    const int*   z       = (const int*)d_in[8];
    const int*   y       = (const int*)d_in[9];
    const int*   x       = (const int*)d_in[10];
    const void*  mask    = d_in[11];
    float* out = (float*)d_out;

    float *featA, *featB, *logits, *S, *att, *ho, *W, *Bt;
    cudaGetSymbolAddress((void**)&featA,  g_featA);
    cudaGetSymbolAddress((void**)&featB,  g_featB);
    cudaGetSymbolAddress((void**)&logits, g_logits);
    cudaGetSymbolAddress((void**)&S,      g_S);
    cudaGetSymbolAddress((void**)&att,    g_att);
    cudaGetSymbolAddress((void**)&ho,     g_ho);
    cudaGetSymbolAddress((void**)&W,      g_W);
    cudaGetSymbolAddress((void**)&Bt,     g_Bt);

    static int attr_done = 0;
    if (!attr_done) {
        cudaFuncSetAttribute(gemm_tf32_cp_kernel<0, true,  false>,
                             cudaFuncAttributeMaxDynamicSharedMemorySize, GEMM_SMEM);
        cudaFuncSetAttribute(gemm_tf32_cp_kernel<0, false, true>,
                             cudaFuncAttributeMaxDynamicSharedMemorySize, GEMM_SMEM);
        cudaFuncSetAttribute(gemm_tf32_cp_kernel<1, false, false>,
                             cudaFuncAttributeMaxDynamicSharedMemorySize, GEMM_SMEM);
        attr_done = 1;
    }

    // 1) mask dtype detection
    detect_mask_kernel<<<1, 256>>>((const unsigned int*)mask, 190000);

    // 2) gather -> featA (A-perm) + featB (B-perm), tf32-rounded
    {
        int total = BB * NN * DD;
        gather_kernel<<<(total + 255) / 256, 256>>>(fv, z, y, x, mask,
                                                    featA, featB, total);
    }

    // 2b) prep attn_w (pad + B-perm + round) and heads weights (B-perm + round)
    prep_attnw_kernel<<<(DD * BT_N + 255) / 256, 256>>>(attn_w, Bt);
    pack_w_kernel<<<(2 * DD * WN + 255) / 256, 256>>>(cls_w, reg_w, W);

    // 3) logits = featA @ Bt + attn_b   (per batch 1000x999, K=768)
    {
        dim3 grid((NM1 + 127) / 128, (NN + 127) / 128, BB);
        gemm_tf32_cp_kernel<0, true, false><<<grid, 128, GEMM_SMEM>>>(
            featA, nullptr, Bt, attn_b, logits,
            NN, NM1, DD, DD, DD, BT_N,
            (size_t)NN * DD, 0, (size_t)NN * NM1);
    }

    // 4) softmax + permuted scatter into padded S
    {
        dim3 grid(NN, BB);
        softmax_scatter_kernel<<<grid, 256>>>(logits, S);
    }

    // 5) att = S @ featB   (per batch 1000x768, K loop 1024, Kb=1000)
    {
        dim3 grid((DD + 127) / 128, (NN + 127) / 128, BB);
        gemm_tf32_cp_kernel<0, false, true><<<grid, 128, GEMM_SMEM>>>(
            S, nullptr, featB, nullptr, att,
            NN, DD, SK_PAD, NN, SK_PAD, DD,
            (size_t)NN * SK_PAD, (size_t)NN * DD, (size_t)NN * DD);
    }

    // 6) heads GEMM: [att|featA] (32000 x 1536) @ W (1536 x 75, padded 128)
    {
        dim3 grid(1, (BB * NN + 127) / 128, 1);
        gemm_tf32_cp_kernel<1, false, false><<<grid, 128, GEMM_SMEM>>>(
            att, featA, W, nullptr, ho,
            BB * NN, HN, 2 * DD, 2 * DD, 0, WN,
            0, 0, 0);
    }

    // 7) heads epilogue
    {
        int total = BB * NN * OUTC;
        heads_epilogue_kernel<<<(total + 255) / 256, 256>>>(ho, cls_b, reg_b,
                                                            anchors, out);
    }
}